// round 1
// baseline (speedup 1.0000x reference)
#include <cuda_runtime.h>

#define BSZ 32
#define NP  64
#define DH  64
#define NN  (NP*NP)   // 4096

// ---------------- device scratch (no allocations allowed) ----------------
__device__ float g_QK[4 * BSZ * NN];    // Q, K1, K2, K3   (each B x N x D, N=D=64)
__device__ float g_att[6 * BSZ * NN];   // attq1, attq2, attq3, Tjk, Tjl, Akl (scaled)
__device__ float g_anchor[BSZ * NP];    // per (b, i) partial sums

__device__ __forceinline__ float ex2_(float x) {
    float y; asm("ex2.approx.ftz.f32 %0, %1;" : "=f"(y) : "f"(x)); return y;
}
__device__ __forceinline__ float rcp_(float x) {
    float y; asm("rcp.approx.ftz.f32 %0, %1;" : "=f"(y) : "f"(x)); return y;
}

// ---------------- k1: the four 3->64 dense layers -------------------------
// grid 128 = B*4, block 256. g_QK[(m*B + b)*4096 + n*64 + d]
__global__ void k1_dense(const float* __restrict__ pts,
                         const float* __restrict__ Wq,  const float* __restrict__ bq,
                         const float* __restrict__ Wk1, const float* __restrict__ bk1,
                         const float* __restrict__ Wk2, const float* __restrict__ bk2,
                         const float* __restrict__ Wk3, const float* __restrict__ bk3) {
    int blk = blockIdx.x;
    int b = blk >> 2, m = blk & 3;
    const float* W; const float* bias;
    if      (m == 0) { W = Wq;  bias = bq;  }
    else if (m == 1) { W = Wk1; bias = bk1; }
    else if (m == 2) { W = Wk2; bias = bk2; }
    else             { W = Wk3; bias = bk3; }
    for (int e = threadIdx.x; e < NN; e += blockDim.x) {
        int n = e >> 6, d = e & 63;
        const float* p = pts + (b * NP + n) * 3;
        float v = fmaf(p[0], W[d],
                  fmaf(p[1], W[64 + d],
                  fmaf(p[2], W[128 + d], bias[d])));
        g_QK[(m * BSZ + b) * NN + e] = v;
    }
}

// ---------------- k2: the six N x N attention matrices ---------------------
// out[r*64+c] = cscale * dot(S1[c,:], S2[r,:]),  cscale = -0.125*log2(e)
// m0: attq1[i][j]=Q_i.K1_j  (S1=K1,S2=Q)     m3: Tjk[k][j]=K1_j.K2_k (S1=K1,S2=K2)
// m1: attq2[i][k]=Q_i.K2_k  (S1=K2,S2=Q)     m4: Tjl[l][j]=K1_j.K3_l (S1=K1,S2=K3)
// m2: attq3[i][l]=Q_i.K3_l  (S1=K3,S2=Q)     m5: Akl[k][l]=K2_k.K3_l (S1=K3,S2=K2)
__global__ void k2_att() {
    __shared__ float S1t[64 * 65];   // transposed, stride-65 padded
    __shared__ float S2s[64 * 64];
    int blk = blockIdx.x;
    int b = blk / 6, m = blk % 6;
    const int s1tab[6] = {1, 2, 3, 1, 1, 3};
    const int s2tab[6] = {0, 0, 0, 2, 3, 2};
    const float* S1 = g_QK + (s1tab[m] * BSZ + b) * NN;
    const float* S2 = g_QK + (s2tab[m] * BSZ + b) * NN;
    for (int t = threadIdx.x; t < NN; t += blockDim.x) {
        int n = t >> 6, d = t & 63;
        S1t[d * 65 + n] = S1[t];
        S2s[t] = S2[t];
    }
    __syncthreads();
    const float cscale = -0.125f * 1.44269504088896340736f;
    for (int e = threadIdx.x; e < NN; e += blockDim.x) {
        int r = e >> 6, c = e & 63;
        float acc = 0.f;
        #pragma unroll
        for (int d = 0; d < 64; d++)
            acc = fmaf(S1t[d * 65 + c], S2s[r * 64 + d], acc);
        g_att[(m * BSZ + b) * NN + e] = acc * cscale;
    }
}

// ---------------- k3: the 537M-iteration gated-det core --------------------
// grid 512 = B * 16 chunks, 4 anchors per block, block 256 (8 warps).
// warp owns k (8 per warp), lanes own l (2 per lane), inner loop over j.
__global__ void __launch_bounds__(256, 4) k3_core(const float* __restrict__ pts) {
    __shared__ float  Tjk_s[NN];        // 16 KB, broadcast reads
    __shared__ float  P_s[64 * 65];     // 16.6 KB, stride-65: conflict-free lane-l reads
    __shared__ float4 D4_s[64];         // disp packed as float4 (one LDS.128 broadcast)
    __shared__ float  aik_s[64];
    __shared__ float  red_s[8];

    int bx = blockIdx.x;
    int b = bx >> 4, chunk = bx & 15;
    int tid = threadIdx.x, warp = tid >> 5, lane = tid & 31;

    const float* attq1 = g_att + (0 * BSZ + b) * NN;
    const float* attq2 = g_att + (1 * BSZ + b) * NN;
    const float* attq3 = g_att + (2 * BSZ + b) * NN;
    const float* Tjk   = g_att + (3 * BSZ + b) * NN;
    const float* Tjl   = g_att + (4 * BSZ + b) * NN;
    const float* Akl   = g_att + (5 * BSZ + b) * NN;

    for (int t = tid; t < NN; t += 256) Tjk_s[t] = Tjk[t];

    for (int a = 0; a < 4; a++) {
        int i = chunk * 4 + a;
        const float* pi = pts + (b * NP + i) * 3;
        float pix = pi[0], piy = pi[1], piz = pi[2];
        if (tid < 64) {
            const float* pp = pts + (b * NP + tid) * 3;
            D4_s[tid]  = make_float4(pp[0] - pix, pp[1] - piy, pp[2] - piz, 0.f);
            aik_s[tid] = attq2[i * 64 + tid];
        }
        for (int t = tid; t < NN; t += 256) {
            int l = t >> 6, j = t & 63;
            P_s[l * 65 + j] = Tjl[t] + attq1[i * 64 + j] + attq3[i * 64 + l];
        }
        __syncthreads();

        float acc = 0.f;
        #pragma unroll 1
        for (int t8 = 0; t8 < 8; t8++) {
            int k = warp + 8 * t8;                  // uniform within warp
            float4 dk = D4_s[k];                    // broadcast
            float  aik = aik_s[k];
            const float* Tk     = Tjk_s + k * 64;
            const float* AklRow = Akl + k * 64;
            #pragma unroll
            for (int l2 = 0; l2 < 2; l2++) {
                int l = lane + 32 * l2;
                float4 dl = D4_s[l];                // conflict-free
                float cx = dk.y * dl.z - dk.z * dl.y;
                float cy = dk.z * dl.x - dk.x * dl.z;
                float cz = dk.x * dl.y - dk.y * dl.x;
                float base = aik + AklRow[l];       // coalesced LDG, L2-hot
                const float* Pl = P_s + l * 65;
                #pragma unroll 16
                for (int j = 0; j < 64; j++) {
                    float4 dj = D4_s[j];            // broadcast LDS.128
                    float e   = base + Tk[j] + Pl[j];   // pre-scaled by -0.125*log2e
                    float det = fmaf(dj.x, cx, fmaf(dj.y, cy, dj.z * cz));
                    float tt  = ex2_(e);            // = exp(-energy)
                    float g   = rcp_(1.f + tt);     // = sigmoid(energy)
                    acc = fmaf(det * det, g, acc);
                }
            }
        }
        // block reduction
        #pragma unroll
        for (int o = 16; o; o >>= 1) acc += __shfl_down_sync(0xffffffffu, acc, o);
        if (lane == 0) red_s[warp] = acc;
        __syncthreads();
        if (tid == 0) {
            float s = 0.f;
            #pragma unroll
            for (int w = 0; w < 8; w++) s += red_s[w];
            g_anchor[b * NP + i] = s;
        }
        __syncthreads();   // protect P_s/D4_s rebuild for next anchor
    }
}

// ---------------- k4: pooled -> gelu MLP head -----------------------------
__global__ void k4_head(const float* __restrict__ W1, const float* __restrict__ b1,
                        const float* __restrict__ W2, const float* __restrict__ b2,
                        float* __restrict__ out) {
    int b = threadIdx.x;
    if (b >= BSZ) return;
    float s = 0.f;
    #pragma unroll
    for (int i = 0; i < NP; i++) s += g_anchor[b * NP + i];
    float pooled = s * (1.f / 16777216.f);   // / (N^3 * N)
    float o = b2[0];
    #pragma unroll
    for (int c = 0; c < 32; c++) {
        float x  = fmaf(pooled, W1[c], b1[c]);
        float x3 = x * x * x;
        float t  = tanhf(0.7978845608028654f * fmaf(0.044715f, x3, x));
        float h  = 0.5f * x * (1.f + t);     // tanh-approx gelu (flax default)
        o = fmaf(h, W2[c], o);
    }
    out[b] = o;
}

// ---------------- launch ---------------------------------------------------
extern "C" void kernel_launch(void* const* d_in, const int* in_sizes, int n_in,
                              void* d_out, int out_size) {
    const float* pts = (const float*)d_in[0];
    const float* Wq  = (const float*)d_in[1];
    const float* bq  = (const float*)d_in[2];
    const float* Wk1 = (const float*)d_in[3];
    const float* bk1 = (const float*)d_in[4];
    const float* Wk2 = (const float*)d_in[5];
    const float* bk2 = (const float*)d_in[6];
    const float* Wk3 = (const float*)d_in[7];
    const float* bk3 = (const float*)d_in[8];
    const float* W1  = (const float*)d_in[9];
    const float* b1  = (const float*)d_in[10];
    const float* W2  = (const float*)d_in[11];
    const float* b2  = (const float*)d_in[12];
    float* out = (float*)d_out;

    k1_dense<<<BSZ * 4, 256>>>(pts, Wq, bq, Wk1, bk1, Wk2, bk2, Wk3, bk3);
    k2_att<<<BSZ * 6, 256>>>();
    k3_core<<<BSZ * 16, 256>>>(pts);
    k4_head<<<1, 32>>>(W1, b1, W2, b2, out);
}

// round 2
// speedup vs baseline: 1.4098x; 1.4098x over previous
#include <cuda_runtime.h>

#define BSZ 32
#define NP  64
#define NN  (NP*NP)   // 4096

typedef unsigned long long u64;

// ---------------- device scratch ----------------
__device__ float g_QK[4 * BSZ * NN];     // Q, K1, K2, K3
__device__ float g_att[6 * BSZ * NN];    // attq1, attq2, attq3, Tjk, Tjl, Akl (pre-scaled by 0.0625)
__device__ float g_anchor2[2 * BSZ * NP];// per (k-half, b, i) partial sums

// ---------------- f32x2 packed helpers ----------------
__device__ __forceinline__ u64 pk2(float lo, float hi) {
    u64 r; asm("mov.b64 %0,{%1,%2};" : "=l"(r) : "f"(lo), "f"(hi)); return r;
}
__device__ __forceinline__ void upk2(float& lo, float& hi, u64 v) {
    asm("mov.b64 {%0,%1},%2;" : "=f"(lo), "=f"(hi) : "l"(v));
}
__device__ __forceinline__ u64 dup2(float x) { return pk2(x, x); }
__device__ __forceinline__ u64 add2(u64 a, u64 b) {
    u64 r; asm("add.rn.f32x2 %0,%1,%2;" : "=l"(r) : "l"(a), "l"(b)); return r;
}
__device__ __forceinline__ u64 mul2(u64 a, u64 b) {
    u64 r; asm("mul.rn.f32x2 %0,%1,%2;" : "=l"(r) : "l"(a), "l"(b)); return r;
}
__device__ __forceinline__ u64 fma2(u64 a, u64 b, u64 c) {
    u64 r; asm("fma.rn.f32x2 %0,%1,%2,%3;" : "=l"(r) : "l"(a), "l"(b), "l"(c)); return r;
}
__device__ __forceinline__ float tanh_(float x) {
    float y; asm("tanh.approx.f32 %0,%1;" : "=f"(y) : "f"(x)); return y;
}

// ---------------- k1: four 3->64 dense layers ----------------
__global__ void k1_dense(const float* __restrict__ pts,
                         const float* __restrict__ Wq,  const float* __restrict__ bq,
                         const float* __restrict__ Wk1, const float* __restrict__ bk1,
                         const float* __restrict__ Wk2, const float* __restrict__ bk2,
                         const float* __restrict__ Wk3, const float* __restrict__ bk3) {
    int blk = blockIdx.x;
    int b = blk >> 2, m = blk & 3;
    const float* W; const float* bias;
    if      (m == 0) { W = Wq;  bias = bq;  }
    else if (m == 1) { W = Wk1; bias = bk1; }
    else if (m == 2) { W = Wk2; bias = bk2; }
    else             { W = Wk3; bias = bk3; }
    for (int e = threadIdx.x; e < NN; e += blockDim.x) {
        int n = e >> 6, d = e & 63;
        const float* p = pts + (b * NP + n) * 3;
        float v = fmaf(p[0], W[d],
                  fmaf(p[1], W[64 + d],
                  fmaf(p[2], W[128 + d], bias[d])));
        g_QK[(m * BSZ + b) * NN + e] = v;
    }
}

// ---------------- k2: six N x N attention matrices ----------------
// out[r*64+c] = 0.0625 * dot(S1[c,:], S2[r,:])   (0.0625 = 0.125 scale * 0.5 tanh-arg)
// m0: attq1[i][j]  m1: attq2[i][k]  m2: attq3[i][l]
// m3: Tjk[k][j]    m4: Tjl[l][j]    m5: Akl[k][l]
__global__ void k2_att() {
    __shared__ float S1t[64 * 65];
    __shared__ float S2s[64 * 64];
    int blk = blockIdx.x;
    int b = blk / 6, m = blk % 6;
    const int s1tab[6] = {1, 2, 3, 1, 1, 3};
    const int s2tab[6] = {0, 0, 0, 2, 3, 2};
    const float* S1 = g_QK + (s1tab[m] * BSZ + b) * NN;
    const float* S2 = g_QK + (s2tab[m] * BSZ + b) * NN;
    for (int t = threadIdx.x; t < NN; t += blockDim.x) {
        int n = t >> 6, d = t & 63;
        S1t[d * 65 + n] = S1[t];
        S2s[t] = S2[t];
    }
    __syncthreads();
    const float cscale = 0.0625f;
    for (int e = threadIdx.x; e < NN; e += blockDim.x) {
        int r = e >> 6, c = e & 63;
        float acc = 0.f;
        #pragma unroll
        for (int d = 0; d < 64; d++)
            acc = fmaf(S1t[d * 65 + c], S2s[r * 64 + d], acc);
        g_att[(m * BSZ + b) * NN + e] = acc * cscale;
    }
}

// ---------------- k3: 537M-eval gated-det core (f32x2 packed) ----------------
// grid 4096 = B(32) x anchors(64) x k-halves(2); block 128 (4 warps).
// warp owns k = k0 + warp + 4*t8; lane owns the (l, l+32) pair, packed in f32x2.
__global__ void __launch_bounds__(128) k3_core(const float* __restrict__ pts) {
    __shared__ float  Tjk_s[32 * 64];    // this block's 32-k slice, rows [k-k0][j]
    __shared__ float2 P2_s[64 * 32];     // [j][lane] = {P(lane,j), P(lane+32,j)}
    __shared__ float4 D4_s[64];          // disp vectors for this anchor
    __shared__ float  red_s[4];

    int bx = blockIdx.x;
    int h  = bx & 1;
    int i  = (bx >> 1) & 63;
    int b  = bx >> 7;
    int k0 = h * 32;
    int tid = threadIdx.x, warp = tid >> 5, lane = tid & 31;

    const float* attq1 = g_att + (0 * BSZ + b) * NN;
    const float* attq2 = g_att + (1 * BSZ + b) * NN;
    const float* attq3 = g_att + (2 * BSZ + b) * NN;
    const float* Tjk   = g_att + (3 * BSZ + b) * NN;
    const float* Tjl   = g_att + (4 * BSZ + b) * NN;
    const float* Akl   = g_att + (5 * BSZ + b) * NN;

    // ---- prep: Tjk slice, disp vectors, fused P(l,j)=Tjl+a1[j]+a3[l] pairs ----
    for (int t = tid; t < 32 * 64; t += 128) Tjk_s[t] = Tjk[k0 * 64 + t];
    {
        const float* pi = pts + (b * NP + i) * 3;
        float pix = pi[0], piy = pi[1], piz = pi[2];
        if (tid < 64) {
            const float* pp = pts + (b * NP + tid) * 3;
            D4_s[tid] = make_float4(pp[0] - pix, pp[1] - piy, pp[2] - piz, 0.f);
        }
    }
    for (int t = tid; t < 2048; t += 128) {
        int lp = t & 31, j = t >> 5;
        float a1j = attq1[i * 64 + j];
        float lo = Tjl[lp * 64 + j]        + a1j + attq3[i * 64 + lp];
        float hi = Tjl[(lp + 32) * 64 + j] + a1j + attq3[i * 64 + lp + 32];
        P2_s[j * 32 + lp] = make_float2(lo, hi);
    }
    __syncthreads();

    // per-lane packed disp for (l=lane, l+32) — loop-invariant registers
    float4 da = D4_s[lane], db = D4_s[lane + 32];
    u64 dlx2 = pk2(da.x, db.x);
    u64 dly2 = pk2(da.y, db.y);
    u64 dlz2 = pk2(da.z, db.z);
    u64 half2c = dup2(0.5f);
    u64 acc2 = pk2(0.f, 0.f);

    #pragma unroll 1
    for (int t8 = 0; t8 < 8; t8++) {
        int k = k0 + warp + 4 * t8;          // uniform within warp
        float4 dk = D4_s[k];                 // LDS.128 broadcast
        float aik = __ldg(attq2 + i * 64 + k);
        const float* AklRow = Akl + k * 64;
        u64 base2 = pk2(aik + __ldg(AklRow + lane), aik + __ldg(AklRow + lane + 32));
        // packed cross(dk, dl) for the lane's l-pair
        u64 cx2 = fma2(dup2(dk.y), dlz2, mul2(dup2(-dk.z), dly2));
        u64 cy2 = fma2(dup2(dk.z), dlx2, mul2(dup2(-dk.x), dlz2));
        u64 cz2 = fma2(dup2(dk.x), dly2, mul2(dup2(-dk.y), dlx2));
        const float* Tk = Tjk_s + (k - k0) * 64;

        #pragma unroll 16
        for (int j = 0; j < 64; j++) {
            float4 dj = D4_s[j];                      // broadcast LDS.128
            float  tk = Tk[j];                        // broadcast LDS
            float2 p  = P2_s[j * 32 + lane];          // conflict-free LDS.64
            u64 e2 = add2(pk2(p.x, p.y), add2(dup2(tk), base2));
            float elo, ehi; upk2(elo, ehi, e2);
            float tlo = tanh_(elo);                   // sigmoid = 0.5 + 0.5*tanh
            float thi = tanh_(ehi);
            u64 det2 = fma2(dup2(dj.x), cx2,
                       fma2(dup2(dj.y), cy2,
                       mul2(dup2(dj.z), cz2)));
            u64 d2 = mul2(det2, det2);
            u64 g2 = fma2(pk2(tlo, thi), half2c, half2c);
            acc2 = fma2(d2, g2, acc2);
        }
    }

    // ---- reduction ----
    float alo, ahi; upk2(alo, ahi, acc2);
    float acc = alo + ahi;
    #pragma unroll
    for (int o = 16; o; o >>= 1) acc += __shfl_down_sync(0xffffffffu, acc, o);
    if (lane == 0) red_s[warp] = acc;
    __syncthreads();
    if (tid == 0) {
        float s = red_s[0] + red_s[1] + red_s[2] + red_s[3];
        g_anchor2[h * BSZ * NP + b * NP + i] = s;
    }
}

// ---------------- k4: pooled -> gelu MLP head (warp per batch) ----------------
__global__ void k4_head(const float* __restrict__ W1, const float* __restrict__ b1,
                        const float* __restrict__ W2, const float* __restrict__ b2,
                        float* __restrict__ out) {
    int warp = threadIdx.x >> 5, lane = threadIdx.x & 31;
    int b = warp;
    float s = g_anchor2[b * 64 + lane] + g_anchor2[b * 64 + lane + 32]
            + g_anchor2[BSZ * NP + b * 64 + lane] + g_anchor2[BSZ * NP + b * 64 + lane + 32];
    #pragma unroll
    for (int o = 16; o; o >>= 1) s += __shfl_xor_sync(0xffffffffu, s, o);
    float pooled = s * (1.f / 16777216.f);         // / (N^3 * N)
    // lane = hidden unit c (32 of them)
    float x  = fmaf(pooled, W1[lane], b1[lane]);
    float x3 = x * x * x;
    float t  = tanhf(0.7978845608028654f * fmaf(0.044715f, x3, x));
    float hc = 0.5f * x * (1.f + t);               // tanh-approx gelu
    float y  = hc * W2[lane];
    #pragma unroll
    for (int o = 16; o; o >>= 1) y += __shfl_xor_sync(0xffffffffu, y, o);
    if (lane == 0) out[b] = y + b2[0];
}

// ---------------- launch ----------------
extern "C" void kernel_launch(void* const* d_in, const int* in_sizes, int n_in,
                              void* d_out, int out_size) {
    const float* pts = (const float*)d_in[0];
    const float* Wq  = (const float*)d_in[1];
    const float* bq  = (const float*)d_in[2];
    const float* Wk1 = (const float*)d_in[3];
    const float* bk1 = (const float*)d_in[4];
    const float* Wk2 = (const float*)d_in[5];
    const float* bk2 = (const float*)d_in[6];
    const float* Wk3 = (const float*)d_in[7];
    const float* bk3 = (const float*)d_in[8];
    const float* W1  = (const float*)d_in[9];
    const float* b1  = (const float*)d_in[10];
    const float* W2  = (const float*)d_in[11];
    const float* b2  = (const float*)d_in[12];
    float* out = (float*)d_out;

    k1_dense<<<BSZ * 4, 256>>>(pts, Wq, bq, Wk1, bk1, Wk2, bk2, Wk3, bk3);
    k2_att<<<BSZ * 6, 256>>>();
    k3_core<<<BSZ * NP * 2, 128>>>(pts);
    k4_head<<<1, BSZ * 32>>>(W1, b1, W2, b2, out);
}